// round 5
// baseline (speedup 1.0000x reference)
#include <cuda_runtime.h>
#include <cuda_bf16.h>
#include <mma.h>
#include <cmath>

using namespace nvcuda;
using bf16 = __nv_bfloat16;

static constexpr int BB = 4, NN = 2048, DD = 1024, GG = 256, QKD = 128, HH = 2048;
static constexpr int MT = BB * NN;   // 8192 rows total
static constexpr int NG = MT / GG;   // 32 groups

// ---------------- scratch (device globals; no allocation allowed) ----------------
__device__ __align__(16) bf16  g_Wh[DD * 2 * HH];
__device__ __align__(16) bf16  g_Wqk[DD * QKD];
__device__ __align__(16) bf16  g_Wout[HH * DD];
__device__ __align__(16) bf16  g_normed[MT * DD];
__device__ __align__(16) bf16  g_h[(long long)MT * 2 * HH];      // v = cols [0,H), gate = cols [H,2H)
__device__ __align__(16) bf16  g_qkbuf[MT * QKD];
__device__ __align__(16) bf16  g_q4[4LL * MT * QKD];             // quad_q, lin_q, quad_k, lin_k
__device__ __align__(16) bf16  g_S[(long long)NG * GG * GG];     // relu(sim/g)^2
__device__ __align__(16) float g_quad[(long long)MT * HH];
__device__ __align__(16) bf16  g_linkv[BB * QKD * HH];
__device__ __align__(16) bf16  g_gated[(long long)MT * HH];
__device__ float g_ctab[NN * 64];
__device__ float g_stab[NN * 64];

// ---------------- small kernels ----------------
__global__ void k_cvt(const float* __restrict__ a, bf16* __restrict__ o, int n) {
    int i = (blockIdx.x * blockDim.x + threadIdx.x) * 4;
    if (i < n) {
        float4 v = *reinterpret_cast<const float4*>(a + i);
        o[i + 0] = __float2bfloat16(v.x);
        o[i + 1] = __float2bfloat16(v.y);
        o[i + 2] = __float2bfloat16(v.z);
        o[i + 3] = __float2bfloat16(v.w);
    }
}

__global__ void k_ln(const float* __restrict__ x, const float* __restrict__ g,
                     const float* __restrict__ b, bf16* __restrict__ out) {
    int row = blockIdx.x;
    int tid = threadIdx.x;
    const float* xr = x + (long long)row * DD;
    float v[4], s = 0.f, ss = 0.f;
#pragma unroll
    for (int i = 0; i < 4; i++) {
        v[i] = xr[tid + i * 256];
        s += v[i];
        ss += v[i] * v[i];
    }
#pragma unroll
    for (int o = 16; o; o >>= 1) {
        s += __shfl_xor_sync(~0u, s, o);
        ss += __shfl_xor_sync(~0u, ss, o);
    }
    __shared__ float sh0[8], sh1[8];
    if ((tid & 31) == 0) { sh0[tid >> 5] = s; sh1[tid >> 5] = ss; }
    __syncthreads();
    if (tid < 32) {
        float a = tid < 8 ? sh0[tid] : 0.f;
        float c = tid < 8 ? sh1[tid] : 0.f;
#pragma unroll
        for (int o = 4; o; o >>= 1) {
            a += __shfl_xor_sync(~0u, a, o);
            c += __shfl_xor_sync(~0u, c, o);
        }
        if (tid == 0) { sh0[0] = a; sh1[0] = c; }
    }
    __syncthreads();
    float mu  = sh0[0] * (1.f / DD);
    float var = sh1[0] * (1.f / DD) - mu * mu;
    float rs  = rsqrtf(var + 1e-5f);
    bf16* orow = out + (long long)row * DD;
#pragma unroll
    for (int i = 0; i < 4; i++) {
        int c = tid + i * 256;
        orow[c] = __float2bfloat16((v[i] - mu) * rs * g[c] + b[c]);
    }
}

__global__ void k_rope_tab(float* __restrict__ ct, float* __restrict__ st) {
    int pos = blockIdx.x, j = threadIdx.x;  // 64 threads
    // inv_freq[j] = 10000^(j/64), computed in double for stability
    double invf = exp((double)j * (9.210340371976184 / 64.0));
    float arg = (float)pos * (float)invf;
    float sv, cv;
    sincosf(arg, &sv, &cv);
    ct[pos * 64 + j] = cv;
    st[pos * 64 + j] = sv;
}

__global__ void k_rope(const bf16* __restrict__ qk, const float* __restrict__ gam,
                       const float* __restrict__ bet, const float* __restrict__ ct,
                       const float* __restrict__ st, bf16* __restrict__ q4) {
    int row = blockIdx.x;
    int tid = threadIdx.x;       // 256
    int head = tid >> 6, j = tid & 63;
    int pos = row & (NN - 1);
    float x1 = __bfloat162float(qk[(long long)row * QKD + j]);
    float x2 = __bfloat162float(qk[(long long)row * QKD + 64 + j]);
    float y1 = x1 * gam[head * QKD + j]      + bet[head * QKD + j];
    float y2 = x2 * gam[head * QKD + 64 + j] + bet[head * QKD + 64 + j];
    float c = ct[pos * 64 + j], s = st[pos * 64 + j];
    long long base = (long long)head * MT * QKD + (long long)row * QKD;
    q4[base + j]      = __float2bfloat16(y1 * c - y2 * s);
    q4[base + 64 + j] = __float2bfloat16(y2 * c + y1 * s);
}

// ---------------- generic wmma bf16 GEMM with fused epilogues ----------------
// EPI: 0 = bias+SiLU -> bf16 ; 1 = (relu(acc*scale))^2 -> bf16 ; 2 = fp32 store ;
//      3 = acc*scale -> bf16 ; 4 = (acc + quad) * gate -> bf16 ; 5 = acc + bias + x -> fp32
struct GemmP {
    const bf16* A; const bf16* B; void* C;
    int M, N, K, lda, ldb, ldc;
    long long sA, sB, sC;
    const float* bias;
    float scale;
    const float* eF; long long seF;           // quad buffer (fp32)
    const bf16* eB;  long long seB; int ldeB; // gate buffer (bf16)
    const float* xres;                        // residual
};

template<bool AROW, bool BROW, int EPI>
__global__ __launch_bounds__(256) void gemm_k(GemmP p) {
    constexpr int BM = 128, BN = 128, BK = 32;
    constexpr int APITCH = BK + 16;   // 48 elems: 16B-aligned rows, mult of 8
    constexpr int BPITCH = BN + 16;   // 144
    __shared__ bf16 As[BM][APITCH];
    __shared__ bf16 Bs[BK][BPITCH];
    __shared__ float Cs[8][256];

    const int z = blockIdx.z;
    const bf16* A  = p.A + z * p.sA;
    const bf16* Bp = p.B + z * p.sB;
    const int bm = blockIdx.y * BM, bn = blockIdx.x * BN;
    const int tid = threadIdx.x, warp = tid >> 5, lane = tid & 31;
    const int wm = (warp >> 2) * 64, wn = (warp & 3) * 32;

    wmma::fragment<wmma::accumulator, 16, 16, 16, float> acc[4][2];
#pragma unroll
    for (int i = 0; i < 4; i++)
#pragma unroll
        for (int j = 0; j < 2; j++) wmma::fill_fragment(acc[i][j], 0.f);

    uint4 ra[2], rb[2];

    auto loadA = [&](int kt) {
        if constexpr (AROW) {
            int r = tid >> 1, c = (tid & 1) * 16;
            const bf16* s = A + (long long)(bm + r) * p.lda + kt + c;
            ra[0] = *reinterpret_cast<const uint4*>(s);
            ra[1] = *reinterpret_cast<const uint4*>(s + 8);
        } else {
#pragma unroll
            for (int u = 0; u < 2; u++) {
                int vi = tid * 2 + u, k = vi >> 4, m0 = (vi & 15) * 8;
                ra[u] = *reinterpret_cast<const uint4*>(A + (long long)(kt + k) * p.lda + bm + m0);
            }
        }
    };
    auto storeA = [&]() {
        if constexpr (AROW) {
            int r = tid >> 1, c = (tid & 1) * 16;
            *reinterpret_cast<uint4*>(&As[r][c])     = ra[0];
            *reinterpret_cast<uint4*>(&As[r][c + 8]) = ra[1];
        } else {
#pragma unroll
            for (int u = 0; u < 2; u++) {
                int vi = tid * 2 + u, k = vi >> 4, m0 = (vi & 15) * 8;
                const bf16* v = reinterpret_cast<const bf16*>(&ra[u]);
#pragma unroll
                for (int e = 0; e < 8; e++) As[m0 + e][k] = v[e];
            }
        }
    };
    auto loadB = [&](int kt) {
        if constexpr (BROW) {
            int r = tid >> 3, c = (tid & 7) * 16;
            const bf16* s = Bp + (long long)(kt + r) * p.ldb + bn + c;
            rb[0] = *reinterpret_cast<const uint4*>(s);
            rb[1] = *reinterpret_cast<const uint4*>(s + 8);
        } else {
#pragma unroll
            for (int u = 0; u < 2; u++) {
                int vi = tid * 2 + u, n = vi >> 2, k0 = (vi & 3) * 8;
                rb[u] = *reinterpret_cast<const uint4*>(Bp + (long long)(bn + n) * p.ldb + kt + k0);
            }
        }
    };
    auto storeB = [&]() {
        if constexpr (BROW) {
            int r = tid >> 3, c = (tid & 7) * 16;
            *reinterpret_cast<uint4*>(&Bs[r][c])     = rb[0];
            *reinterpret_cast<uint4*>(&Bs[r][c + 8]) = rb[1];
        } else {
#pragma unroll
            for (int u = 0; u < 2; u++) {
                int vi = tid * 2 + u, n = vi >> 2, k0 = (vi & 3) * 8;
                const bf16* v = reinterpret_cast<const bf16*>(&rb[u]);
#pragma unroll
                for (int e = 0; e < 8; e++) Bs[k0 + e][n] = v[e];
            }
        }
    };

    loadA(0); loadB(0);
    for (int kt = 0; kt < p.K; kt += BK) {
        storeA(); storeB();
        __syncthreads();
        if (kt + BK < p.K) { loadA(kt + BK); loadB(kt + BK); }
#pragma unroll
        for (int kk = 0; kk < BK; kk += 16) {
            wmma::fragment<wmma::matrix_a, 16, 16, 16, bf16, wmma::row_major> af[4];
            wmma::fragment<wmma::matrix_b, 16, 16, 16, bf16, wmma::row_major> bfr[2];
#pragma unroll
            for (int i = 0; i < 4; i++) wmma::load_matrix_sync(af[i], &As[wm + i * 16][kk], APITCH);
#pragma unroll
            for (int j = 0; j < 2; j++) wmma::load_matrix_sync(bfr[j], &Bs[kk][wn + j * 16], BPITCH);
#pragma unroll
            for (int i = 0; i < 4; i++)
#pragma unroll
                for (int j = 0; j < 2; j++) wmma::mma_sync(acc[i][j], af[i], bfr[j], acc[i][j]);
        }
        __syncthreads();
    }

    // epilogue: round-trip each 16x16 fragment through per-warp smem scratch
#pragma unroll
    for (int i = 0; i < 4; i++) {
#pragma unroll
        for (int j = 0; j < 2; j++) {
            wmma::store_matrix_sync(Cs[warp], acc[i][j], 16, wmma::mem_row_major);
            __syncwarp();
            int gr0 = bm + wm + i * 16, gc0 = bn + wn + j * 16;
#pragma unroll
            for (int l = 0; l < 8; l++) {
                int idx = l * 32 + lane;
                int gr = gr0 + (idx >> 4), gc = gc0 + (idx & 15);
                float v = Cs[warp][idx];
                if constexpr (EPI == 0) {
                    float t = v + p.bias[gc];
                    t = t / (1.f + expf(-t));
                    ((bf16*)p.C + z * p.sC)[(long long)gr * p.ldc + gc] = __float2bfloat16(t);
                } else if constexpr (EPI == 1) {
                    float t = v * p.scale;
                    t = t > 0.f ? t : 0.f;
                    t *= t;
                    ((bf16*)p.C + z * p.sC)[(long long)gr * p.ldc + gc] = __float2bfloat16(t);
                } else if constexpr (EPI == 2) {
                    ((float*)p.C + z * p.sC)[(long long)gr * p.ldc + gc] = v;
                } else if constexpr (EPI == 3) {
                    ((bf16*)p.C + z * p.sC)[(long long)gr * p.ldc + gc] = __float2bfloat16(v * p.scale);
                } else if constexpr (EPI == 4) {
                    float q  = (p.eF + z * p.seF)[(long long)gr * p.ldc + gc];
                    float gt = __bfloat162float((p.eB + z * p.seB)[(long long)gr * p.ldeB + gc]);
                    ((bf16*)p.C + z * p.sC)[(long long)gr * p.ldc + gc] = __float2bfloat16((v + q) * gt);
                } else {
                    float t = v + p.bias[gc] + p.xres[(long long)gr * p.ldc + gc];
                    ((float*)p.C)[(long long)gr * p.ldc + gc] = t;
                }
            }
            __syncwarp();
        }
    }
}

// ---------------- host launcher ----------------
extern "C" void kernel_launch(void* const* d_in, const int* in_sizes, int n_in,
                              void* d_out, int out_size) {
    const float* x   = (const float*)d_in[0];
    const float* lng = (const float*)d_in[1];
    const float* lnb = (const float*)d_in[2];
    const float* Wh  = (const float*)d_in[3];
    const float* bh  = (const float*)d_in[4];
    const float* Wq  = (const float*)d_in[5];
    const float* bq  = (const float*)d_in[6];
    const float* osg = (const float*)d_in[7];
    const float* osb = (const float*)d_in[8];
    const float* Wo  = (const float*)d_in[9];
    const float* bo  = (const float*)d_in[10];

    void *pWh, *pWq, *pWo, *pN, *pH, *pQK, *pQ4, *pS, *pQd, *pKV, *pGt, *pCt, *pSt;
    cudaGetSymbolAddress(&pWh, g_Wh);
    cudaGetSymbolAddress(&pWq, g_Wqk);
    cudaGetSymbolAddress(&pWo, g_Wout);
    cudaGetSymbolAddress(&pN,  g_normed);
    cudaGetSymbolAddress(&pH,  g_h);
    cudaGetSymbolAddress(&pQK, g_qkbuf);
    cudaGetSymbolAddress(&pQ4, g_q4);
    cudaGetSymbolAddress(&pS,  g_S);
    cudaGetSymbolAddress(&pQd, g_quad);
    cudaGetSymbolAddress(&pKV, g_linkv);
    cudaGetSymbolAddress(&pGt, g_gated);
    cudaGetSymbolAddress(&pCt, g_ctab);
    cudaGetSymbolAddress(&pSt, g_stab);

    // weight conversions fp32 -> bf16
    k_cvt<<<(DD * 2 * HH) / 4 / 256, 256>>>(Wh, (bf16*)pWh, DD * 2 * HH);
    k_cvt<<<(DD * QKD) / 4 / 256,   256>>>(Wq, (bf16*)pWq, DD * QKD);
    k_cvt<<<(HH * DD) / 4 / 256,    256>>>(Wo, (bf16*)pWo, HH * DD);

    // layernorm
    k_ln<<<MT, 256>>>(x, lng, lnb, (bf16*)pN);

    GemmP p;

    // GEMM1: h = silu(normed @ W_hidden + b_hidden)  [8192 x 4096]
    p = GemmP{};
    p.A = (bf16*)pN; p.B = (bf16*)pWh; p.C = pH;
    p.M = MT; p.N = 2 * HH; p.K = DD; p.lda = DD; p.ldb = 2 * HH; p.ldc = 2 * HH;
    p.bias = bh;
    gemm_k<true, true, 0><<<dim3(2 * HH / 128, MT / 128, 1), 256>>>(p);

    // GEMM2: qk = silu(normed @ W_qk + b_qk)  [8192 x 128]
    p = GemmP{};
    p.A = (bf16*)pN; p.B = (bf16*)pWq; p.C = pQK;
    p.M = MT; p.N = QKD; p.K = DD; p.lda = DD; p.ldb = QKD; p.ldc = QKD;
    p.bias = bq;
    gemm_k<true, true, 0><<<dim3(1, MT / 128, 1), 256>>>(p);

    // offset-scale + rope
    k_rope_tab<<<NN, 64>>>((float*)pCt, (float*)pSt);
    k_rope<<<MT, 256>>>((const bf16*)pQK, osg, osb, (const float*)pCt, (const float*)pSt, (bf16*)pQ4);

    bf16* q4 = (bf16*)pQ4;

    // sim: S = relu(Qq @ Qk^T / g)^2 per group  [32 x 256 x 256]
    p = GemmP{};
    p.A = q4; p.B = q4 + 2LL * MT * QKD; p.C = pS;
    p.M = GG; p.N = GG; p.K = QKD; p.lda = QKD; p.ldb = QKD; p.ldc = GG;
    p.sA = (long long)GG * QKD; p.sB = (long long)GG * QKD; p.sC = (long long)GG * GG;
    p.scale = 1.f / GG;
    gemm_k<true, false, 1><<<dim3(2, 2, NG), 256>>>(p);

    // quad_out = S @ V per group  -> fp32 [8192 x 2048]
    p = GemmP{};
    p.A = (bf16*)pS; p.B = (bf16*)pH; p.C = pQd;
    p.M = GG; p.N = HH; p.K = GG; p.lda = GG; p.ldb = 2 * HH; p.ldc = HH;
    p.sA = (long long)GG * GG; p.sB = (long long)GG * 2 * HH; p.sC = (long long)GG * HH;
    gemm_k<true, true, 2><<<dim3(HH / 128, GG / 128, NG), 256>>>(p);

    // lin_kv = (lin_k^T @ V) / N per batch  [4 x 128 x 2048]
    p = GemmP{};
    p.A = q4 + 3LL * MT * QKD; p.B = (bf16*)pH; p.C = pKV;
    p.M = QKD; p.N = HH; p.K = NN; p.lda = QKD; p.ldb = 2 * HH; p.ldc = HH;
    p.sA = (long long)NN * QKD; p.sB = (long long)NN * 2 * HH; p.sC = (long long)QKD * HH;
    p.scale = 1.f / NN;
    gemm_k<false, true, 3><<<dim3(HH / 128, 1, BB), 256>>>(p);

    // gated = (lin_q @ lin_kv + quad_out) * gate  -> bf16 [8192 x 2048]
    p = GemmP{};
    p.A = q4 + 1LL * MT * QKD; p.B = (bf16*)pKV; p.C = pGt;
    p.M = NN; p.N = HH; p.K = QKD; p.lda = QKD; p.ldb = HH; p.ldc = HH;
    p.sA = (long long)NN * QKD; p.sB = (long long)QKD * HH; p.sC = (long long)NN * HH;
    p.eF = (const float*)pQd; p.seF = (long long)NN * HH;
    p.eB = (const bf16*)pH + HH; p.seB = (long long)NN * 2 * HH; p.ldeB = 2 * HH;
    gemm_k<true, true, 4><<<dim3(HH / 128, NN / 128, BB), 256>>>(p);

    // final: out = gated @ W_out + b_out + x  -> fp32 [8192 x 1024]
    p = GemmP{};
    p.A = (bf16*)pGt; p.B = (bf16*)pWo; p.C = d_out;
    p.M = MT; p.N = DD; p.K = HH; p.lda = HH; p.ldb = DD; p.ldc = DD;
    p.bias = bo; p.xres = x;
    gemm_k<true, true, 5><<<dim3(DD / 128, MT / 128, 1), 256>>>(p);
}

// round 10
// speedup vs baseline: 1.7074x; 1.7074x over previous
#include <cuda_runtime.h>
#include <cuda_bf16.h>
#include <cstdint>
#include <cmath>

using bf16 = __nv_bfloat16;

static constexpr int BB = 4, NN = 2048, DD = 1024, GG = 256, QKD = 128, HH = 2048;
static constexpr int MT = BB * NN;   // 8192 tokens
static constexpr int NG = MT / GG;   // 32 groups
static constexpr int STAGES = 4;
static constexpr int STAGE_BYTES = 32768;                 // 16KB A + 16KB B
static constexpr int SMEM_DYN = 1024 + STAGES * STAGE_BYTES;

// ---------------- scratch (device globals) ----------------
__device__ __align__(16) bf16  g_WhT[2 * HH * DD];          // [4096,1024] K-major
__device__ __align__(16) bf16  g_WqkT[QKD * DD];            // [128,1024]
__device__ __align__(16) bf16  g_WoutT[DD * HH];            // [1024,2048]
__device__ __align__(16) bf16  g_normed[MT * DD];
__device__ __align__(16) bf16  g_h[(long long)MT * 2 * HH]; // v cols [0,H), gate [H,2H)
__device__ __align__(16) bf16  g_vT[(long long)HH * MT];    // V^T [H, MT]
__device__ __align__(16) bf16  g_qkbuf[MT * QKD];
__device__ __align__(16) bf16  g_q3[3LL * MT * QKD];        // quad_q, lin_q, quad_k
__device__ __align__(16) bf16  g_linkT[(long long)QKD * MT];// lin_k^T [QK, MT]
__device__ __align__(16) bf16  g_S[(long long)NG * GG * GG];
__device__ __align__(16) bf16  g_quad[(long long)MT * HH];
__device__ __align__(16) bf16  g_kvT[BB * HH * QKD];        // (lin_kv)^T per batch [H, QK]
__device__ __align__(16) bf16  g_gated[(long long)MT * HH];
__device__ float g_ctab[NN * 64];
__device__ float g_stab[NN * 64];

// ---------------- PTX helpers ----------------
__device__ __forceinline__ uint32_t su32(const void* p) {
    uint32_t a;
    asm("{ .reg .u64 t; cvta.to.shared.u64 t, %1; cvt.u32.u64 %0, t; }" : "=r"(a) : "l"(p));
    return a;
}
#define SW128(o) ((o) ^ (((o) >> 3) & 0x70))

__device__ __forceinline__ void cpa16(uint32_t d, const void* s) {
    asm volatile("cp.async.cg.shared.global [%0], [%1], 16;" :: "r"(d), "l"(s));
}
__device__ __forceinline__ void cpa_commit() { asm volatile("cp.async.commit_group;"); }
__device__ __forceinline__ void cpa_wait2()  { asm volatile("cp.async.wait_group 2;"); }

__device__ __forceinline__ void ldsm4(uint32_t* r, uint32_t a) {
    asm volatile("ldmatrix.sync.aligned.m8n8.x4.shared.b16 {%0,%1,%2,%3}, [%4];"
                 : "=r"(r[0]), "=r"(r[1]), "=r"(r[2]), "=r"(r[3]) : "r"(a));
}
__device__ __forceinline__ void mma16816(float* c, const uint32_t* a, uint32_t b0, uint32_t b1) {
    asm volatile("mma.sync.aligned.m16n8k16.row.col.f32.bf16.bf16.f32 "
                 "{%0,%1,%2,%3}, {%4,%5,%6,%7}, {%8,%9}, {%0,%1,%2,%3};"
                 : "+f"(c[0]), "+f"(c[1]), "+f"(c[2]), "+f"(c[3])
                 : "r"(a[0]), "r"(a[1]), "r"(a[2]), "r"(a[3]), "r"(b0), "r"(b1));
}
__device__ __forceinline__ uint32_t packbf2(float a, float b) {
    __nv_bfloat162 t = __floats2bfloat162_rn(a, b);
    return *reinterpret_cast<uint32_t*>(&t);
}

// ---------------- small kernels ----------------
__global__ void k_cvt_t(const float* __restrict__ a, bf16* __restrict__ o, int R, int C) {
    // a: [R,C] fp32 -> o: [C,R] bf16
    __shared__ float t[32][33];
    int c0 = blockIdx.x * 32, r0 = blockIdx.y * 32;
    int tx = threadIdx.x & 31, ty = threadIdx.x >> 5;
#pragma unroll
    for (int i = 0; i < 32; i += 8)
        t[ty + i][tx] = a[(long long)(r0 + ty + i) * C + c0 + tx];
    __syncthreads();
#pragma unroll
    for (int i = 0; i < 32; i += 8)
        o[(long long)(c0 + ty + i) * R + r0 + tx] = __float2bfloat16(t[tx][ty + i]);
}

__global__ void k_transV(const bf16* __restrict__ h, bf16* __restrict__ vT) {
    __shared__ bf16 t[32][33];
    int c0 = blockIdx.x * 32, r0 = blockIdx.y * 32;   // c0 over H, r0 over MT
    int tx = threadIdx.x & 31, ty = threadIdx.x >> 5;
#pragma unroll
    for (int i = 0; i < 32; i += 8)
        t[ty + i][tx] = h[(long long)(r0 + ty + i) * (2 * HH) + c0 + tx];
    __syncthreads();
#pragma unroll
    for (int i = 0; i < 32; i += 8)
        vT[(long long)(c0 + ty + i) * MT + r0 + tx] = t[tx][ty + i];
}

__global__ void k_ln(const float* __restrict__ x, const float* __restrict__ g,
                     const float* __restrict__ b, bf16* __restrict__ out) {
    int row = blockIdx.x, tid = threadIdx.x;
    const float* xr = x + (long long)row * DD;
    float v[4], s = 0.f, ss = 0.f;
#pragma unroll
    for (int i = 0; i < 4; i++) { v[i] = xr[tid + i * 256]; s += v[i]; ss += v[i] * v[i]; }
#pragma unroll
    for (int o = 16; o; o >>= 1) { s += __shfl_xor_sync(~0u, s, o); ss += __shfl_xor_sync(~0u, ss, o); }
    __shared__ float sh0[8], sh1[8];
    if ((tid & 31) == 0) { sh0[tid >> 5] = s; sh1[tid >> 5] = ss; }
    __syncthreads();
    if (tid < 32) {
        float a = tid < 8 ? sh0[tid] : 0.f, c = tid < 8 ? sh1[tid] : 0.f;
#pragma unroll
        for (int o = 4; o; o >>= 1) { a += __shfl_xor_sync(~0u, a, o); c += __shfl_xor_sync(~0u, c, o); }
        if (tid == 0) { sh0[0] = a; sh1[0] = c; }
    }
    __syncthreads();
    float mu = sh0[0] * (1.f / DD);
    float var = sh1[0] * (1.f / DD) - mu * mu;
    float rs = rsqrtf(var + 1e-5f);
    bf16* orow = out + (long long)row * DD;
#pragma unroll
    for (int i = 0; i < 4; i++) {
        int c = tid + i * 256;
        orow[c] = __float2bfloat16((v[i] - mu) * rs * g[c] + b[c]);
    }
}

__global__ void k_rope_tab(float* __restrict__ ct, float* __restrict__ st) {
    int pos = blockIdx.x, j = threadIdx.x;
    double invf = exp((double)j * (9.210340371976184 / 64.0));
    float arg = (float)pos * (float)invf;
    float sv, cv;
    sincosf(arg, &sv, &cv);
    ct[pos * 64 + j] = cv;
    st[pos * 64 + j] = sv;
}

__global__ void k_rope(const bf16* __restrict__ qk, const float* __restrict__ gam,
                       const float* __restrict__ bet, const float* __restrict__ ct,
                       const float* __restrict__ st, bf16* __restrict__ q3,
                       bf16* __restrict__ linkT) {
    int row = blockIdx.x, tid = threadIdx.x;
    int head = tid >> 6, j = tid & 63;
    int pos = row & (NN - 1);
    float x1 = __bfloat162float(qk[(long long)row * QKD + j]);
    float x2 = __bfloat162float(qk[(long long)row * QKD + 64 + j]);
    float y1 = x1 * gam[head * QKD + j]      + bet[head * QKD + j];
    float y2 = x2 * gam[head * QKD + 64 + j] + bet[head * QKD + 64 + j];
    float c = ct[pos * 64 + j], s = st[pos * 64 + j];
    bf16 r1 = __float2bfloat16(y1 * c - y2 * s);
    bf16 r2 = __float2bfloat16(y2 * c + y1 * s);
    if (head == 3) {   // lin_k transposed: [QK, MT]
        linkT[(long long)j * MT + row]        = r1;
        linkT[(long long)(64 + j) * MT + row] = r2;
    } else {
        long long base = (long long)head * MT * QKD + (long long)row * QKD;
        q3[base + j]      = r1;
        q3[base + 64 + j] = r2;
    }
}

// ---------------- mma.sync bf16 GEMM (sm80-style pipeline) ----------------
// All operands K-major: A [M,K] row-major, B [N,K] row-major. Tile 128x128x64.
// EPI: 0 = bias+SiLU->bf16 ; 1 = relu(v*scale)^2->bf16 ; 3 = v*scale->bf16 ;
//      4 = (v + quad)*gate->bf16 ; 5 = v + bias + x -> fp32
struct GemmP {
    const bf16* A; const bf16* B; void* C;
    int K, lda, ldb, ldc;
    long long sA, sB, sC;
    const float* bias;
    float scale;
    const bf16* eQ; long long seQ;             // quad (bf16), ld = ldc
    const bf16* eG; long long seG; int ldeG;   // gate (bf16)
    const float* xres;
};

template<int EPI>
__global__ __launch_bounds__(256, 1) void mm_gemm(GemmP p) {
    extern __shared__ char smem_raw[];
    uint32_t sb = su32(smem_raw);
    const uint32_t buf = (sb + 1023u) & ~1023u;
    const int tid = threadIdx.x, warp = tid >> 5, lane = tid & 31;
    const int z = blockIdx.z;
    const bf16* A = p.A + z * p.sA;
    const bf16* B = p.B + z * p.sB;
    const int bm = blockIdx.y * 128, bn = blockIdx.x * 128;
    const int T = p.K >> 6;

    auto issue = [&](int t) {
        uint32_t ab = buf + (t % STAGES) * STAGE_BYTES;
        uint32_t bb = ab + 16384;
        int kt = t * 64;
#pragma unroll
        for (int u = 0; u < 4; u++) {
            int id = u * 256 + tid;
            int r = id >> 3, c = (id & 7) * 8;
            uint32_t so = SW128(r * 128 + c * 2);
            cpa16(ab + so, A + (long long)(bm + r) * p.lda + kt + c);
            cpa16(bb + so, B + (long long)(bn + r) * p.ldb + kt + c);
        }
        cpa_commit();
    };

    float acc[2][8][4];
#pragma unroll
    for (int i = 0; i < 2; i++)
#pragma unroll
        for (int j = 0; j < 8; j++)
#pragma unroll
            for (int k = 0; k < 4; k++) acc[i][j][k] = 0.f;

    // per-thread swizzled ldmatrix base offsets (within a stage tile)
    const int wm = warp >> 1, wn = warp & 1;
    const uint32_t offA = (uint32_t)((wm * 32 + (lane & 15)) * 128 + (lane >> 4) * 16);
    const uint32_t swA  = offA ^ ((offA >> 3) & 0x70);
    const uint32_t offB = (uint32_t)((wn * 64 + ((lane >> 4) << 3) + (lane & 7)) * 128 +
                                     ((lane >> 3) & 1) * 16);
    const uint32_t swB  = offB ^ ((offB >> 3) & 0x70);

#pragma unroll 1
    for (int i = 0; i < STAGES - 1; i++) {
        if (i < T) issue(i); else cpa_commit();
    }

#pragma unroll 1
    for (int t = 0; t < T; t++) {
        cpa_wait2();
        __syncthreads();
        if (t + STAGES - 1 < T) issue(t + STAGES - 1); else cpa_commit();

        uint32_t ab = buf + (t % STAGES) * STAGE_BYTES;
        uint32_t bb = ab + 16384;
#pragma unroll
        for (int ks = 0; ks < 4; ks++) {
            // k-step advance must be XORed into the swizzled offset (pre-swizzle
            // bits 5-6 are clear; adding post-swizzle can carry into the row bits)
            uint32_t abase = ab + (swA ^ (uint32_t)(32 * ks));
            uint32_t bbase = bb + (swB ^ (uint32_t)(32 * ks));
            uint32_t af[2][4], bfr[4][4];
#pragma unroll
            for (int mi = 0; mi < 2; mi++) ldsm4(af[mi], abase + mi * 2048);
#pragma unroll
            for (int j = 0; j < 4; j++)   ldsm4(bfr[j], bbase + j * 2048);
#pragma unroll
            for (int mi = 0; mi < 2; mi++)
#pragma unroll
                for (int nf = 0; nf < 8; nf++) {
                    const uint32_t* bp = &bfr[nf >> 1][(nf & 1) * 2];
                    mma16816(acc[mi][nf], af[mi], bp[0], bp[1]);
                }
        }
    }

    // ---- epilogue: direct register -> gmem ----
    const int r_base = bm + wm * 32 + (lane >> 2);
    const int c_base = bn + wn * 64 + (lane & 3) * 2;

#pragma unroll
    for (int mi = 0; mi < 2; mi++) {
#pragma unroll
        for (int h = 0; h < 2; h++) {
            const int gr = r_base + mi * 16 + h * 8;
#pragma unroll
            for (int nf = 0; nf < 8; nf++) {
                const int gc = c_base + nf * 8;
                float v0 = acc[mi][nf][h * 2 + 0];
                float v1 = acc[mi][nf][h * 2 + 1];

                if constexpr (EPI == 0) {
                    float t0 = v0 + p.bias[gc], t1 = v1 + p.bias[gc + 1];
                    t0 = t0 / (1.f + expf(-t0));
                    t1 = t1 / (1.f + expf(-t1));
                    *reinterpret_cast<uint32_t*>((bf16*)p.C + z * p.sC +
                        (long long)gr * p.ldc + gc) = packbf2(t0, t1);
                } else if constexpr (EPI == 1) {
                    float t0 = v0 * p.scale, t1 = v1 * p.scale;
                    t0 = t0 > 0.f ? t0 : 0.f;
                    t1 = t1 > 0.f ? t1 : 0.f;
                    *reinterpret_cast<uint32_t*>((bf16*)p.C + z * p.sC +
                        (long long)gr * p.ldc + gc) = packbf2(t0 * t0, t1 * t1);
                } else if constexpr (EPI == 3) {
                    *reinterpret_cast<uint32_t*>((bf16*)p.C + z * p.sC +
                        (long long)gr * p.ldc + gc) = packbf2(v0 * p.scale, v1 * p.scale);
                } else if constexpr (EPI == 4) {
                    uint32_t qv = *reinterpret_cast<const uint32_t*>(
                        p.eQ + z * p.seQ + (long long)gr * p.ldc + gc);
                    uint32_t gv = *reinterpret_cast<const uint32_t*>(
                        p.eG + z * p.seG + (long long)gr * p.ldeG + gc);
                    float2 qf = __bfloat1622float2(*reinterpret_cast<__nv_bfloat162*>(&qv));
                    float2 gf = __bfloat1622float2(*reinterpret_cast<__nv_bfloat162*>(&gv));
                    *reinterpret_cast<uint32_t*>((bf16*)p.C + z * p.sC +
                        (long long)gr * p.ldc + gc) =
                        packbf2((v0 + qf.x) * gf.x, (v1 + qf.y) * gf.y);
                } else {   // EPI 5: v + bias + x -> fp32
                    const float* xr = p.xres + (long long)gr * p.ldc + gc;
                    float2 o;
                    o.x = v0 + p.bias[gc] + xr[0];
                    o.y = v1 + p.bias[gc + 1] + xr[1];
                    *reinterpret_cast<float2*>((float*)p.C +
                        (long long)gr * p.ldc + gc) = o;
                }
            }
        }
    }
}

// ---------------- host launcher ----------------
extern "C" void kernel_launch(void* const* d_in, const int* in_sizes, int n_in,
                              void* d_out, int out_size) {
    const float* x   = (const float*)d_in[0];
    const float* lng = (const float*)d_in[1];
    const float* lnb = (const float*)d_in[2];
    const float* Wh  = (const float*)d_in[3];
    const float* bh  = (const float*)d_in[4];
    const float* Wq  = (const float*)d_in[5];
    const float* bq  = (const float*)d_in[6];
    const float* osg = (const float*)d_in[7];
    const float* osb = (const float*)d_in[8];
    const float* Wo  = (const float*)d_in[9];
    const float* bo  = (const float*)d_in[10];

    void *pWh, *pWq, *pWo, *pN, *pH, *pVT, *pQK, *pQ3, *pLK, *pS, *pQd, *pKV, *pGt, *pCt, *pSt;
    cudaGetSymbolAddress(&pWh, g_WhT);
    cudaGetSymbolAddress(&pWq, g_WqkT);
    cudaGetSymbolAddress(&pWo, g_WoutT);
    cudaGetSymbolAddress(&pN,  g_normed);
    cudaGetSymbolAddress(&pH,  g_h);
    cudaGetSymbolAddress(&pVT, g_vT);
    cudaGetSymbolAddress(&pQK, g_qkbuf);
    cudaGetSymbolAddress(&pQ3, g_q3);
    cudaGetSymbolAddress(&pLK, g_linkT);
    cudaGetSymbolAddress(&pS,  g_S);
    cudaGetSymbolAddress(&pQd, g_quad);
    cudaGetSymbolAddress(&pKV, g_kvT);
    cudaGetSymbolAddress(&pGt, g_gated);
    cudaGetSymbolAddress(&pCt, g_ctab);
    cudaGetSymbolAddress(&pSt, g_stab);

    cudaFuncSetAttribute(mm_gemm<0>, cudaFuncAttributeMaxDynamicSharedMemorySize, SMEM_DYN);
    cudaFuncSetAttribute(mm_gemm<1>, cudaFuncAttributeMaxDynamicSharedMemorySize, SMEM_DYN);
    cudaFuncSetAttribute(mm_gemm<3>, cudaFuncAttributeMaxDynamicSharedMemorySize, SMEM_DYN);
    cudaFuncSetAttribute(mm_gemm<4>, cudaFuncAttributeMaxDynamicSharedMemorySize, SMEM_DYN);
    cudaFuncSetAttribute(mm_gemm<5>, cudaFuncAttributeMaxDynamicSharedMemorySize, SMEM_DYN);

    // transposed weight conversions fp32 -> bf16
    k_cvt_t<<<dim3(2 * HH / 32, DD / 32), 256>>>(Wh, (bf16*)pWh, DD, 2 * HH);
    k_cvt_t<<<dim3(QKD / 32, DD / 32),    256>>>(Wq, (bf16*)pWq, DD, QKD);
    k_cvt_t<<<dim3(DD / 32, HH / 32),     256>>>(Wo, (bf16*)pWo, HH, DD);

    k_ln<<<MT, 256>>>(x, lng, lnb, (bf16*)pN);

    GemmP p;

    // GEMM1: h = silu(normed @ Wh + bh)  [8192 x 4096], K=1024
    p = GemmP{};
    p.A = (bf16*)pN; p.B = (bf16*)pWh; p.C = pH;
    p.K = DD; p.lda = DD; p.ldb = DD; p.ldc = 2 * HH;
    p.bias = bh;
    mm_gemm<0><<<dim3(2 * HH / 128, MT / 128, 1), 256, SMEM_DYN>>>(p);

    // GEMM2: qk = silu(normed @ Wqk + bq)  [8192 x 128], K=1024
    p = GemmP{};
    p.A = (bf16*)pN; p.B = (bf16*)pWq; p.C = pQK;
    p.K = DD; p.lda = DD; p.ldb = DD; p.ldc = QKD;
    p.bias = bq;
    mm_gemm<0><<<dim3(1, MT / 128, 1), 256, SMEM_DYN>>>(p);

    k_rope_tab<<<NN, 64>>>((float*)pCt, (float*)pSt);
    k_rope<<<MT, 256>>>((const bf16*)pQK, osg, osb, (const float*)pCt, (const float*)pSt,
                        (bf16*)pQ3, (bf16*)pLK);
    k_transV<<<dim3(HH / 32, MT / 32), 256>>>((const bf16*)pH, (bf16*)pVT);

    bf16* q3 = (bf16*)pQ3;

    // sim: S = relu(Qq @ Qk^T / G)^2 per group  [32 x 256 x 256], K=128
    p = GemmP{};
    p.A = q3; p.B = q3 + 2LL * MT * QKD; p.C = pS;
    p.K = QKD; p.lda = QKD; p.ldb = QKD; p.ldc = GG;
    p.sA = (long long)GG * QKD; p.sB = (long long)GG * QKD; p.sC = (long long)GG * GG;
    p.scale = 1.f / GG;
    mm_gemm<1><<<dim3(2, 2, NG), 256, SMEM_DYN>>>(p);

    // quad_out = S @ V per group -> bf16 [8192 x 2048], K=256 (B = V^T, K-major)
    p = GemmP{};
    p.A = (bf16*)pS; p.B = (bf16*)pVT; p.C = pQd;
    p.K = GG; p.lda = GG; p.ldb = MT; p.ldc = HH;
    p.sA = (long long)GG * GG; p.sB = GG; p.sC = (long long)GG * HH;
    p.scale = 1.f;
    mm_gemm<3><<<dim3(HH / 128, GG / 128, NG), 256, SMEM_DYN>>>(p);

    // kvT = (V^T @ lin_k) / NN per batch  [4 x 2048 x 128], K=2048
    p = GemmP{};
    p.A = (bf16*)pVT; p.B = (bf16*)pLK; p.C = pKV;
    p.K = NN; p.lda = MT; p.ldb = MT; p.ldc = QKD;
    p.sA = NN; p.sB = NN; p.sC = (long long)HH * QKD;
    p.scale = 1.f / NN;
    mm_gemm<3><<<dim3(1, HH / 128, BB), 256, SMEM_DYN>>>(p);

    // gated = (lin_q @ kvT^T + quad) * gate -> bf16 [8192 x 2048], K=128
    p = GemmP{};
    p.A = q3 + 1LL * MT * QKD; p.B = (bf16*)pKV; p.C = pGt;
    p.K = QKD; p.lda = QKD; p.ldb = QKD; p.ldc = HH;
    p.sA = (long long)NN * QKD; p.sB = (long long)HH * QKD; p.sC = (long long)NN * HH;
    p.eQ = (const bf16*)pQd; p.seQ = (long long)NN * HH;
    p.eG = (const bf16*)pH + HH; p.seG = (long long)NN * 2 * HH; p.ldeG = 2 * HH;
    mm_gemm<4><<<dim3(HH / 128, NN / 128, BB), 256, SMEM_DYN>>>(p);

    // final: out = gated @ Wout + bo + x -> fp32 [8192 x 1024], K=2048
    p = GemmP{};
    p.A = (bf16*)pGt; p.B = (bf16*)pWo; p.C = d_out;
    p.K = HH; p.lda = HH; p.ldb = HH; p.ldc = DD;
    p.bias = bo; p.xres = x;
    mm_gemm<5><<<dim3(DD / 128, MT / 128, 1), 256, SMEM_DYN>>>(p);
}

// round 14
// speedup vs baseline: 2.3564x; 1.3802x over previous
#include <cuda_runtime.h>
#include <cuda_bf16.h>
#include <cstdint>
#include <cmath>

using bf16 = __nv_bfloat16;

static constexpr int BB = 4, NN = 2048, DD = 1024, GG = 256, QKD = 128, HH = 2048;
static constexpr int MT = BB * NN;   // 8192 tokens
static constexpr int NG = MT / GG;   // 32 groups
static constexpr int NC = 2 * HH + QKD;   // 4224 combined hidden+qk cols
static constexpr int STAGES = 3;
static constexpr int STAGE_BYTES = 32768;                 // 16KB A + 16KB B
static constexpr int SMEM_DYN = 1024 + STAGES * STAGE_BYTES;   // 99328

// ---------------- scratch (device globals) ----------------
__device__ __align__(16) bf16  g_WcT[NC * DD];              // [4224,1024] K-major (Wh | Wqk)
__device__ __align__(16) bf16  g_WoutT[DD * HH];            // [1024,2048]
__device__ __align__(16) float g_biasC[NC];                 // bh | bq
__device__ __align__(16) bf16  g_normed[MT * DD];
__device__ __align__(16) bf16  g_h2[(long long)MT * NC];    // v [0,H) | gate [H,2H) | qk [2H,2H+128)
__device__ __align__(16) bf16  g_vT[(long long)HH * MT];    // V^T [H, MT]
__device__ __align__(16) bf16  g_q3[3LL * MT * QKD];        // quad_q, lin_q, quad_k
__device__ __align__(16) bf16  g_linkT[(long long)QKD * MT];// lin_k^T [QK, MT]
__device__ __align__(16) bf16  g_S[(long long)NG * GG * GG];
__device__ __align__(16) bf16  g_kvT[BB * HH * QKD];        // (lin_kv)^T per batch [H, QK]
__device__ __align__(16) bf16  g_gated[(long long)MT * HH];
__device__ float g_ctab[NN * 64];
__device__ float g_stab[NN * 64];

// ---------------- PTX helpers ----------------
__device__ __forceinline__ uint32_t su32(const void* p) {
    uint32_t a;
    asm("{ .reg .u64 t; cvta.to.shared.u64 t, %1; cvt.u32.u64 %0, t; }" : "=r"(a) : "l"(p));
    return a;
}
#define SW128(o) ((o) ^ (((o) >> 3) & 0x70))

__device__ __forceinline__ void cpa16(uint32_t d, const void* s) {
    asm volatile("cp.async.cg.shared.global [%0], [%1], 16;" :: "r"(d), "l"(s));
}
__device__ __forceinline__ void cpa_commit() { asm volatile("cp.async.commit_group;"); }
__device__ __forceinline__ void cpa_wait1()  { asm volatile("cp.async.wait_group 1;"); }

__device__ __forceinline__ void ldsm4(uint32_t* r, uint32_t a) {
    asm volatile("ldmatrix.sync.aligned.m8n8.x4.shared.b16 {%0,%1,%2,%3}, [%4];"
                 : "=r"(r[0]), "=r"(r[1]), "=r"(r[2]), "=r"(r[3]) : "r"(a));
}
__device__ __forceinline__ void mma16816(float* c, const uint32_t* a, uint32_t b0, uint32_t b1) {
    asm volatile("mma.sync.aligned.m16n8k16.row.col.f32.bf16.bf16.f32 "
                 "{%0,%1,%2,%3}, {%4,%5,%6,%7}, {%8,%9}, {%0,%1,%2,%3};"
                 : "+f"(c[0]), "+f"(c[1]), "+f"(c[2]), "+f"(c[3])
                 : "r"(a[0]), "r"(a[1]), "r"(a[2]), "r"(a[3]), "r"(b0), "r"(b1));
}
__device__ __forceinline__ uint32_t packbf2(float a, float b) {
    __nv_bfloat162 t = __floats2bfloat162_rn(a, b);
    return *reinterpret_cast<uint32_t*>(&t);
}

// ---------------- small kernels ----------------
__global__ void k_cvt_t(const float* __restrict__ a, bf16* __restrict__ o, int R, int C) {
    // a: [R,C] fp32 -> o: [C,R] bf16
    __shared__ float t[32][33];
    int c0 = blockIdx.x * 32, r0 = blockIdx.y * 32;
    int tx = threadIdx.x & 31, ty = threadIdx.x >> 5;
#pragma unroll
    for (int i = 0; i < 32; i += 8)
        t[ty + i][tx] = a[(long long)(r0 + ty + i) * C + c0 + tx];
    __syncthreads();
#pragma unroll
    for (int i = 0; i < 32; i += 8)
        o[(long long)(c0 + ty + i) * R + r0 + tx] = __float2bfloat16(t[tx][ty + i]);
}

__global__ void k_biasc(const float* __restrict__ bh, const float* __restrict__ bq,
                        float* __restrict__ o) {
    int i = blockIdx.x * 256 + threadIdx.x;
    if (i < NC) o[i] = (i < 2 * HH) ? bh[i] : bq[i - 2 * HH];
}

__global__ void k_transV(const bf16* __restrict__ h2, bf16* __restrict__ vT) {
    __shared__ bf16 t[32][33];
    int c0 = blockIdx.x * 32, r0 = blockIdx.y * 32;   // c0 over H, r0 over MT
    int tx = threadIdx.x & 31, ty = threadIdx.x >> 5;
#pragma unroll
    for (int i = 0; i < 32; i += 8)
        t[ty + i][tx] = h2[(long long)(r0 + ty + i) * NC + c0 + tx];
    __syncthreads();
#pragma unroll
    for (int i = 0; i < 32; i += 8)
        vT[(long long)(c0 + ty + i) * MT + r0 + tx] = t[tx][ty + i];
}

__global__ void k_ln(const float* __restrict__ x, const float* __restrict__ g,
                     const float* __restrict__ b, bf16* __restrict__ out) {
    int row = blockIdx.x, tid = threadIdx.x;
    const float* xr = x + (long long)row * DD;
    float v[4], s = 0.f, ss = 0.f;
#pragma unroll
    for (int i = 0; i < 4; i++) { v[i] = xr[tid + i * 256]; s += v[i]; ss += v[i] * v[i]; }
#pragma unroll
    for (int o = 16; o; o >>= 1) { s += __shfl_xor_sync(~0u, s, o); ss += __shfl_xor_sync(~0u, ss, o); }
    __shared__ float sh0[8], sh1[8];
    if ((tid & 31) == 0) { sh0[tid >> 5] = s; sh1[tid >> 5] = ss; }
    __syncthreads();
    if (tid < 32) {
        float a = tid < 8 ? sh0[tid] : 0.f, c = tid < 8 ? sh1[tid] : 0.f;
#pragma unroll
        for (int o = 4; o; o >>= 1) { a += __shfl_xor_sync(~0u, a, o); c += __shfl_xor_sync(~0u, c, o); }
        if (tid == 0) { sh0[0] = a; sh1[0] = c; }
    }
    __syncthreads();
    float mu = sh0[0] * (1.f / DD);
    float var = sh1[0] * (1.f / DD) - mu * mu;
    float rs = rsqrtf(var + 1e-5f);
    bf16* orow = out + (long long)row * DD;
#pragma unroll
    for (int i = 0; i < 4; i++) {
        int c = tid + i * 256;
        orow[c] = __float2bfloat16((v[i] - mu) * rs * g[c] + b[c]);
    }
}

__global__ void k_rope_tab(float* __restrict__ ct, float* __restrict__ st) {
    int pos = blockIdx.x, j = threadIdx.x;
    double invf = exp((double)j * (9.210340371976184 / 64.0));
    float arg = (float)pos * (float)invf;
    float sv, cv;
    sincosf(arg, &sv, &cv);
    ct[pos * 64 + j] = cv;
    st[pos * 64 + j] = sv;
}

__global__ void k_rope(const bf16* __restrict__ h2, const float* __restrict__ gam,
                       const float* __restrict__ bet, const float* __restrict__ ct,
                       const float* __restrict__ st, bf16* __restrict__ q3,
                       bf16* __restrict__ linkT) {
    int row = blockIdx.x, tid = threadIdx.x;
    int head = tid >> 6, j = tid & 63;
    int pos = row & (NN - 1);
    const bf16* qk = h2 + (long long)row * NC + 2 * HH;   // qk cols of combined buffer
    float x1 = __bfloat162float(qk[j]);
    float x2 = __bfloat162float(qk[64 + j]);
    float y1 = x1 * gam[head * QKD + j]      + bet[head * QKD + j];
    float y2 = x2 * gam[head * QKD + 64 + j] + bet[head * QKD + 64 + j];
    float c = ct[pos * 64 + j], s = st[pos * 64 + j];
    bf16 r1 = __float2bfloat16(y1 * c - y2 * s);
    bf16 r2 = __float2bfloat16(y2 * c + y1 * s);
    if (head == 3) {   // lin_k transposed: [QK, MT]
        linkT[(long long)j * MT + row]        = r1;
        linkT[(long long)(64 + j) * MT + row] = r2;
    } else {
        long long base = (long long)head * MT * QKD + (long long)row * QKD;
        q3[base + j]      = r1;
        q3[base + 64 + j] = r2;
    }
}

// ---------------- mma.sync bf16 GEMM (sm80-style pipeline, occ 2) ----------------
// All operands K-major: A [M,K] row-major, B [N,K] row-major. Tile 128x128x64.
// EPI: 0 = bias+SiLU->bf16 ; 1 = relu(v*scale)^2->bf16 ; 3 = v*scale->bf16 ;
//      5 = v + bias + x -> fp32 ; 6 = two-phase (S@V then lin_q@kvT) * gate -> bf16
struct GemmP {
    const bf16* A; const bf16* B; void* C;
    int K, lda, ldb, ldc;
    long long sA, sB, sC;
    const float* bias;
    float scale;
    const bf16* A2; const bf16* B2;            // EPI 6 phase-2 operands
    int K2, lda2, ldb2;
    long long sB2;
    const bf16* eG; int ldeG;                  // gate (bf16)
    const float* xres;
};

template<int EPI>
__global__ __launch_bounds__(256, 2) void mm_gemm(GemmP p) {
    extern __shared__ char smem_raw[];
    uint32_t sb = su32(smem_raw);
    const uint32_t buf = (sb + 1023u) & ~1023u;
    const int tid = threadIdx.x, warp = tid >> 5, lane = tid & 31;
    const int z = blockIdx.z;
    const int bm = blockIdx.y * 128, bn = blockIdx.x * 128;

    const bf16* A = p.A + z * p.sA;
    const bf16* B;
    if constexpr (EPI == 6) B = p.B + (long long)(bm >> 8) * GG;   // group's V^T cols
    else                    B = p.B + z * p.sB;

    const int T1 = p.K >> 6;
    int T = T1;
    const bf16* A2 = nullptr; const bf16* B2 = nullptr;
    if constexpr (EPI == 6) {
        T += p.K2 >> 6;
        A2 = p.A2;
        B2 = p.B2 + (long long)(bm >> 11) * p.sB2;   // batch's kvT
    }

    auto issue = [&](int t) {
        const bf16* Ap; const bf16* Bp; int lda, ldb, kt;
        if (EPI == 6 && t >= T1) {
            Ap = A2; Bp = B2; lda = p.lda2; ldb = p.ldb2; kt = (t - T1) * 64;
        } else {
            Ap = A; Bp = B; lda = p.lda; ldb = p.ldb; kt = t * 64;
        }
        uint32_t ab = buf + (t % STAGES) * STAGE_BYTES;
        uint32_t bb = ab + 16384;
#pragma unroll
        for (int u = 0; u < 4; u++) {
            int id = u * 256 + tid;
            int r = id >> 3, c = (id & 7) * 8;
            uint32_t so = SW128(r * 128 + c * 2);
            cpa16(ab + so, Ap + (long long)(bm + r) * lda + kt + c);
            cpa16(bb + so, Bp + (long long)(bn + r) * ldb + kt + c);
        }
        cpa_commit();
    };

    float acc[2][8][4];
#pragma unroll
    for (int i = 0; i < 2; i++)
#pragma unroll
        for (int j = 0; j < 8; j++)
#pragma unroll
            for (int k = 0; k < 4; k++) acc[i][j][k] = 0.f;

    // per-thread swizzled ldmatrix base offsets (within a stage tile)
    const int wm = warp >> 1, wn = warp & 1;
    const uint32_t offA = (uint32_t)((wm * 32 + (lane & 15)) * 128 + (lane >> 4) * 16);
    const uint32_t swA  = offA ^ ((offA >> 3) & 0x70);
    const uint32_t offB = (uint32_t)((wn * 64 + ((lane >> 4) << 3) + (lane & 7)) * 128 +
                                     ((lane >> 3) & 1) * 16);
    const uint32_t swB  = offB ^ ((offB >> 3) & 0x70);

#pragma unroll 1
    for (int i = 0; i < STAGES - 1; i++) {
        if (i < T) issue(i); else cpa_commit();
    }

#pragma unroll 1
    for (int t = 0; t < T; t++) {
        cpa_wait1();
        __syncthreads();
        if (t + STAGES - 1 < T) issue(t + STAGES - 1); else cpa_commit();

        uint32_t ab = buf + (t % STAGES) * STAGE_BYTES;
        uint32_t bb = ab + 16384;
#pragma unroll
        for (int ks = 0; ks < 4; ks++) {
            // k-step advance XORed into the swizzled offset (pre-swizzle bits 5-6
            // are clear; adding post-swizzle can carry into the row bits)
            uint32_t abase = ab + (swA ^ (uint32_t)(32 * ks));
            uint32_t bbase = bb + (swB ^ (uint32_t)(32 * ks));
            uint32_t af[2][4], bfr[4][4];
#pragma unroll
            for (int mi = 0; mi < 2; mi++) ldsm4(af[mi], abase + mi * 2048);
#pragma unroll
            for (int j = 0; j < 4; j++)   ldsm4(bfr[j], bbase + j * 2048);
#pragma unroll
            for (int mi = 0; mi < 2; mi++)
#pragma unroll
                for (int nf = 0; nf < 8; nf++) {
                    const uint32_t* bp = &bfr[nf >> 1][(nf & 1) * 2];
                    mma16816(acc[mi][nf], af[mi], bp[0], bp[1]);
                }
        }
    }

    // ---- epilogue: direct register -> gmem ----
    const int r_base = bm + wm * 32 + (lane >> 2);
    const int c_base = bn + wn * 64 + (lane & 3) * 2;

#pragma unroll
    for (int mi = 0; mi < 2; mi++) {
#pragma unroll
        for (int h = 0; h < 2; h++) {
            const int gr = r_base + mi * 16 + h * 8;
#pragma unroll
            for (int nf = 0; nf < 8; nf++) {
                const int gc = c_base + nf * 8;
                float v0 = acc[mi][nf][h * 2 + 0];
                float v1 = acc[mi][nf][h * 2 + 1];

                if constexpr (EPI == 0) {
                    float t0 = v0 + p.bias[gc], t1 = v1 + p.bias[gc + 1];
                    t0 = t0 / (1.f + expf(-t0));
                    t1 = t1 / (1.f + expf(-t1));
                    *reinterpret_cast<uint32_t*>((bf16*)p.C + z * p.sC +
                        (long long)gr * p.ldc + gc) = packbf2(t0, t1);
                } else if constexpr (EPI == 1) {
                    float t0 = v0 * p.scale, t1 = v1 * p.scale;
                    t0 = t0 > 0.f ? t0 : 0.f;
                    t1 = t1 > 0.f ? t1 : 0.f;
                    *reinterpret_cast<uint32_t*>((bf16*)p.C + z * p.sC +
                        (long long)gr * p.ldc + gc) = packbf2(t0 * t0, t1 * t1);
                } else if constexpr (EPI == 3) {
                    *reinterpret_cast<uint32_t*>((bf16*)p.C + z * p.sC +
                        (long long)gr * p.ldc + gc) = packbf2(v0 * p.scale, v1 * p.scale);
                } else if constexpr (EPI == 6) {
                    uint32_t gv = *reinterpret_cast<const uint32_t*>(
                        p.eG + (long long)gr * p.ldeG + gc);
                    float2 gf = __bfloat1622float2(*reinterpret_cast<__nv_bfloat162*>(&gv));
                    *reinterpret_cast<uint32_t*>((bf16*)p.C +
                        (long long)gr * p.ldc + gc) = packbf2(v0 * gf.x, v1 * gf.y);
                } else {   // EPI 5: v + bias + x -> fp32
                    const float* xr = p.xres + (long long)gr * p.ldc + gc;
                    float2 o;
                    o.x = v0 + p.bias[gc] + xr[0];
                    o.y = v1 + p.bias[gc + 1] + xr[1];
                    *reinterpret_cast<float2*>((float*)p.C +
                        (long long)gr * p.ldc + gc) = o;
                }
            }
        }
    }
}

// ---------------- host launcher ----------------
extern "C" void kernel_launch(void* const* d_in, const int* in_sizes, int n_in,
                              void* d_out, int out_size) {
    const float* x   = (const float*)d_in[0];
    const float* lng = (const float*)d_in[1];
    const float* lnb = (const float*)d_in[2];
    const float* Wh  = (const float*)d_in[3];
    const float* bh  = (const float*)d_in[4];
    const float* Wq  = (const float*)d_in[5];
    const float* bq  = (const float*)d_in[6];
    const float* osg = (const float*)d_in[7];
    const float* osb = (const float*)d_in[8];
    const float* Wo  = (const float*)d_in[9];
    const float* bo  = (const float*)d_in[10];

    void *pWc, *pWo_, *pBc, *pN, *pH2, *pVT, *pQ3, *pLK, *pS, *pKV, *pGt, *pCt, *pSt;
    cudaGetSymbolAddress(&pWc, g_WcT);
    cudaGetSymbolAddress(&pWo_, g_WoutT);
    cudaGetSymbolAddress(&pBc, g_biasC);
    cudaGetSymbolAddress(&pN,  g_normed);
    cudaGetSymbolAddress(&pH2, g_h2);
    cudaGetSymbolAddress(&pVT, g_vT);
    cudaGetSymbolAddress(&pQ3, g_q3);
    cudaGetSymbolAddress(&pLK, g_linkT);
    cudaGetSymbolAddress(&pS,  g_S);
    cudaGetSymbolAddress(&pKV, g_kvT);
    cudaGetSymbolAddress(&pGt, g_gated);
    cudaGetSymbolAddress(&pCt, g_ctab);
    cudaGetSymbolAddress(&pSt, g_stab);

    cudaFuncSetAttribute(mm_gemm<0>, cudaFuncAttributeMaxDynamicSharedMemorySize, SMEM_DYN);
    cudaFuncSetAttribute(mm_gemm<1>, cudaFuncAttributeMaxDynamicSharedMemorySize, SMEM_DYN);
    cudaFuncSetAttribute(mm_gemm<3>, cudaFuncAttributeMaxDynamicSharedMemorySize, SMEM_DYN);
    cudaFuncSetAttribute(mm_gemm<5>, cudaFuncAttributeMaxDynamicSharedMemorySize, SMEM_DYN);
    cudaFuncSetAttribute(mm_gemm<6>, cudaFuncAttributeMaxDynamicSharedMemorySize, SMEM_DYN);

    // transposed weight conversions: Wh -> rows [0,4096), Wqk -> rows [4096,4224)
    k_cvt_t<<<dim3(2 * HH / 32, DD / 32), 256>>>(Wh, (bf16*)pWc, DD, 2 * HH);
    k_cvt_t<<<dim3(QKD / 32, DD / 32),    256>>>(Wq, (bf16*)pWc + 2LL * HH * DD, DD, QKD);
    k_cvt_t<<<dim3(DD / 32, HH / 32),     256>>>(Wo, (bf16*)pWo_, HH, DD);
    k_biasc<<<(NC + 255) / 256, 256>>>(bh, bq, (float*)pBc);

    k_ln<<<MT, 256>>>(x, lng, lnb, (bf16*)pN);

    GemmP p;

    // GEMM A: h2 = silu(normed @ [Wh|Wqk] + [bh|bq])  [8192 x 4224], K=1024
    p = GemmP{};
    p.A = (bf16*)pN; p.B = (bf16*)pWc; p.C = pH2;
    p.K = DD; p.lda = DD; p.ldb = DD; p.ldc = NC;
    p.bias = (const float*)pBc;
    mm_gemm<0><<<dim3(NC / 128, MT / 128, 1), 256, SMEM_DYN>>>(p);

    k_rope_tab<<<NN, 64>>>((float*)pCt, (float*)pSt);
    k_rope<<<MT, 256>>>((const bf16*)pH2, osg, osb, (const float*)pCt, (const float*)pSt,
                        (bf16*)pQ3, (bf16*)pLK);
    k_transV<<<dim3(HH / 32, MT / 32), 256>>>((const bf16*)pH2, (bf16*)pVT);

    bf16* q3 = (bf16*)pQ3;

    // sim: S = relu(Qq @ Qk^T / G)^2 per group  [32 x 256 x 256], K=128
    p = GemmP{};
    p.A = q3; p.B = q3 + 2LL * MT * QKD; p.C = pS;
    p.K = QKD; p.lda = QKD; p.ldb = QKD; p.ldc = GG;
    p.sA = (long long)GG * QKD; p.sB = (long long)GG * QKD; p.sC = (long long)GG * GG;
    p.scale = 1.f / GG;
    mm_gemm<1><<<dim3(2, 2, NG), 256, SMEM_DYN>>>(p);

    // kvT = (V^T @ lin_k) / NN per batch  [4 x 2048 x 128], K=2048
    p = GemmP{};
    p.A = (bf16*)pVT; p.B = (bf16*)pLK; p.C = pKV;
    p.K = NN; p.lda = MT; p.ldb = MT; p.ldc = QKD;
    p.sA = NN; p.sB = NN; p.sC = (long long)HH * QKD;
    p.scale = 1.f / NN;
    mm_gemm<3><<<dim3(1, HH / 128, BB), 256, SMEM_DYN>>>(p);

    // fused: gated = (S@V_group + lin_q@kvT^T) * gate -> bf16 [8192 x 2048]
    // phase 1: A=S (per group, K=256), B=V^T (group cols); phase 2: A=lin_q, B=kvT (K=128)
    p = GemmP{};
    p.A = (bf16*)pS; p.lda = GG; p.K = GG; p.sA = 0;   // A + bm*256 == S[group] + (bm%256)*256
    p.B = (bf16*)pVT; p.ldb = MT;
    p.A2 = q3 + 1LL * MT * QKD; p.lda2 = QKD;
    p.B2 = (bf16*)pKV; p.ldb2 = QKD; p.K2 = QKD; p.sB2 = (long long)HH * QKD;
    p.C = pGt; p.ldc = HH;
    p.eG = (const bf16*)pH2 + HH; p.ldeG = NC;
    mm_gemm<6><<<dim3(HH / 128, MT / 128, 1), 256, SMEM_DYN>>>(p);

    // final: out = gated @ Wout + bo + x -> fp32 [8192 x 1024], K=2048
    p = GemmP{};
    p.A = (bf16*)pGt; p.B = (bf16*)pWo_; p.C = d_out;
    p.K = HH; p.lda = HH; p.ldb = HH; p.ldc = DD;
    p.bias = bo; p.xres = x;
    mm_gemm<5><<<dim3(DD / 128, MT / 128, 1), 256, SMEM_DYN>>>(p);
}